// round 3
// baseline (speedup 1.0000x reference)
#include <cuda_runtime.h>
#include <math.h>
#include <stdint.h>

#define NN      100000
#define NE      2000000
#define HH      64
#define TPB     256
#define NTILES_MAX ((NE/128) + 2)

// ---------------- device scratch ----------------
__device__ __align__(16) float g_h[NN * HH];
__device__ __align__(16) float g_agg[NN * HH];   // invariant: zero on entry to each edge phase
__device__ int g_src[NE + 256];
__device__ int g_dst[NE + 256];
__device__ int g_cnt1;
__device__ int g_cur0, g_cur1;
__device__ int g_b0p, g_ntiles;

__device__ __forceinline__ float sigf(float v) { return 1.f / (1.f + __expf(-v)); }

__device__ __forceinline__ void red_add_v4(float* p, float a, float b, float c, float d) {
    asm volatile("red.global.add.v4.f32 [%0], {%1, %2, %3, %4};"
                 :: "l"(p), "f"(a), "f"(b), "f"(c), "f"(d) : "memory");
}

// ---------------- input projection: h = relu(LN(x@W+b)) ----------------
__global__ __launch_bounds__(TPB) void tg_input(const float* __restrict__ x,
    const float* __restrict__ in_w, const float* __restrict__ in_b,
    const float* __restrict__ ln_g, const float* __restrict__ ln_b)
{
    __shared__ float sw[256], sb[64], sg[64], sbn[64];
    int tid = threadIdx.x;
    if (tid < 256) sw[tid] = in_w[tid];
    if (tid < 64) { sb[tid] = in_b[tid]; sg[tid] = ln_g[tid]; sbn[tid] = ln_b[tid]; }
    __syncthreads();
    int lane = tid & 31;
    int warpsTotal = gridDim.x * (TPB / 32);
    for (int node = blockIdx.x * (TPB/32) + (tid >> 5); node < NN; node += warpsTotal) {
        float4 xv = *(const float4*)(x + node * 4);
        int c0 = lane * 2;
        float v0 = sb[c0]   + xv.x*sw[c0]   + xv.y*sw[64+c0]   + xv.z*sw[128+c0]   + xv.w*sw[192+c0];
        float v1 = sb[c0+1] + xv.x*sw[c0+1] + xv.y*sw[64+c0+1] + xv.z*sw[128+c0+1] + xv.w*sw[192+c0+1];
        float s = v0 + v1;
        #pragma unroll
        for (int o = 16; o; o >>= 1) s += __shfl_xor_sync(0xffffffffu, s, o);
        float mu = s * (1.0f/64.0f);
        float d0 = v0 - mu, d1 = v1 - mu;
        float q = d0*d0 + d1*d1;
        #pragma unroll
        for (int o = 16; o; o >>= 1) q += __shfl_xor_sync(0xffffffffu, q, o);
        float inv = rsqrtf(q * (1.0f/64.0f) + 1e-5f);
        g_h[node*64 + c0]   = fmaxf(d0*inv*sg[c0]   + sbn[c0],   0.f);
        g_h[node*64 + c0+1] = fmaxf(d1*inv*sg[c0+1] + sbn[c0+1], 0.f);
    }
}

// ---------------- edge partition by type (2 buckets, tile-aligned) ----------------
__global__ __launch_bounds__(TPB) void tg_count(const int* __restrict__ et) {
    __shared__ int sm[8];
    int tid = threadIdx.x;
    int s = 0;
    for (int e = blockIdx.x*TPB + tid; e < NE; e += gridDim.x*TPB) s += et[e];
    #pragma unroll
    for (int o = 16; o; o >>= 1) s += __shfl_xor_sync(0xffffffffu, s, o);
    if ((tid & 31) == 0) sm[tid >> 5] = s;
    __syncthreads();
    if (tid == 0) { int t = 0; for (int j = 0; j < 8; j++) t += sm[j]; atomicAdd(&g_cnt1, t); }
}

__global__ void tg_scan() {
    int c1 = g_cnt1; g_cnt1 = 0;
    int c0 = NE - c1;
    int b0p = (c0 + 127) & ~127;
    int end1 = b0p + c1;
    int nt = (end1 + 127) >> 7;
    g_b0p = b0p; g_ntiles = nt;
    g_cur0 = 0; g_cur1 = b0p;
    for (int i = c0; i < b0p; i++) { g_src[i] = 0; g_dst[i] = NN; }
    for (int i = end1; i < nt*128; i++) { g_src[i] = 0; g_dst[i] = NN; }
}

__global__ __launch_bounds__(TPB) void tg_scatter(const int* __restrict__ et,
                                                  const int* __restrict__ ei) {
    int lane = threadIdx.x & 31;
    unsigned lt = (1u << lane) - 1u;
    for (int e = blockIdx.x*TPB + threadIdx.x; e < NE; e += gridDim.x*TPB) {
        int t = et[e];                                   // NE % 32 == 0 -> full warps
        unsigned m1 = __ballot_sync(0xffffffffu, t);
        int n1 = __popc(m1);
        int b0 = 0, b1 = 0;
        if (lane == 0) {
            b0 = atomicAdd(&g_cur0, 32 - n1);
            b1 = atomicAdd(&g_cur1, n1);
        }
        b0 = __shfl_sync(0xffffffffu, b0, 0);
        b1 = __shfl_sync(0xffffffffu, b1, 0);
        int pos = t ? (b1 + __popc(m1 & lt)) : (b0 + __popc(~m1 & lt));
        g_src[pos] = ei[e];
        g_dst[pos] = ei[NE + e];
    }
}

// ---------------- edge MLP + scatter-add (per layer) ----------------
// smem: mi 16384 | W1 8192 | h1 8192 | W2 4096 | b1 64 | b2 64  (floats)
#define EDGE_SMEM ((16384 + 8192 + 8192 + 4096 + 64 + 64) * 4)

__global__ __launch_bounds__(TPB, 1) void tg_edge(const float* __restrict__ w1g,
    const float* __restrict__ b1g, const float* __restrict__ w2g, const float* __restrict__ b2g)
{
    int tile = blockIdx.x;
    if (tile >= g_ntiles) return;
    int t = (tile * 128 >= g_b0p) ? 1 : 0;

    extern __shared__ float sm[];
    float* smi = sm;               // [128][128]
    float* sW1 = sm + 16384;       // [128][64]
    float* sh1 = sW1 + 8192;       // [128][64]
    float* sW2 = sh1 + 8192;       // [64][64]
    float* sb1 = sW2 + 4096;       // [64]
    float* sb2 = sb1 + 64;         // [64]

    int tid = threadIdx.x;
    const float* w1 = w1g + t * 8192;
    const float* w2 = w2g + t * 4096;
    for (int i = tid; i < 2048; i += TPB) ((float4*)sW1)[i] = ((const float4*)w1)[i];
    for (int i = tid; i < 1024; i += TPB) ((float4*)sW2)[i] = ((const float4*)w2)[i];
    if (tid < 64) { sb1[tid] = b1g[t*64 + tid]; sb2[tid] = b2g[t*64 + tid]; }

    // gather mi = [h[src] | h[dst]] : 128 rows x 32 float4
    int base = tile * 128;
    for (int i = tid; i < 4096; i += TPB) {
        int e = i >> 5, c = i & 31;
        int idx = (c < 16) ? g_src[base + e] : g_dst[base + e];
        if (idx >= NN) idx = 0;
        ((float4*)smi)[e*32 + c] = ((const float4*)(g_h + (size_t)idx*64))[c & 15];
    }
    __syncthreads();

    int eg = tid >> 4, cg = tid & 15;           // 16 edge groups x 16 col groups
    float acc[8][4];
    #pragma unroll
    for (int e = 0; e < 8; e++) { acc[e][0]=0.f; acc[e][1]=0.f; acc[e][2]=0.f; acc[e][3]=0.f; }

    const float* miB = smi + eg*8*128;
    const float* wB  = sW1 + cg*4;
    for (int k = 0; k < 128; k += 4) {
        float4 w0 = *(const float4*)(wB + (k+0)*64);
        float4 wA = *(const float4*)(wB + (k+1)*64);
        float4 wBv= *(const float4*)(wB + (k+2)*64);
        float4 wC = *(const float4*)(wB + (k+3)*64);
        #pragma unroll
        for (int e = 0; e < 8; e++) {
            float4 m = *(const float4*)(miB + e*128 + k);
            acc[e][0] = fmaf(m.x,w0.x,fmaf(m.y,wA.x,fmaf(m.z,wBv.x,fmaf(m.w,wC.x,acc[e][0]))));
            acc[e][1] = fmaf(m.x,w0.y,fmaf(m.y,wA.y,fmaf(m.z,wBv.y,fmaf(m.w,wC.y,acc[e][1]))));
            acc[e][2] = fmaf(m.x,w0.z,fmaf(m.y,wA.z,fmaf(m.z,wBv.z,fmaf(m.w,wC.z,acc[e][2]))));
            acc[e][3] = fmaf(m.x,w0.w,fmaf(m.y,wA.w,fmaf(m.z,wBv.w,fmaf(m.w,wC.w,acc[e][3]))));
        }
    }
    #pragma unroll
    for (int e = 0; e < 8; e++)
        #pragma unroll
        for (int j = 0; j < 4; j++)
            sh1[(eg*8+e)*64 + cg*4 + j] = fmaxf(acc[e][j] + sb1[cg*4+j], 0.f);
    __syncthreads();

    #pragma unroll
    for (int e = 0; e < 8; e++) { acc[e][0]=0.f; acc[e][1]=0.f; acc[e][2]=0.f; acc[e][3]=0.f; }
    const float* h1B = sh1 + eg*8*64;
    const float* w2B = sW2 + cg*4;
    for (int k = 0; k < 64; k += 4) {
        float4 w0 = *(const float4*)(w2B + (k+0)*64);
        float4 wA = *(const float4*)(w2B + (k+1)*64);
        float4 wBv= *(const float4*)(w2B + (k+2)*64);
        float4 wC = *(const float4*)(w2B + (k+3)*64);
        #pragma unroll
        for (int e = 0; e < 8; e++) {
            float4 m = *(const float4*)(h1B + e*64 + k);
            acc[e][0] = fmaf(m.x,w0.x,fmaf(m.y,wA.x,fmaf(m.z,wBv.x,fmaf(m.w,wC.x,acc[e][0]))));
            acc[e][1] = fmaf(m.x,w0.y,fmaf(m.y,wA.y,fmaf(m.z,wBv.y,fmaf(m.w,wC.y,acc[e][1]))));
            acc[e][2] = fmaf(m.x,w0.z,fmaf(m.y,wA.z,fmaf(m.z,wBv.z,fmaf(m.w,wC.z,acc[e][2]))));
            acc[e][3] = fmaf(m.x,w0.w,fmaf(m.y,wA.w,fmaf(m.z,wBv.w,fmaf(m.w,wC.w,acc[e][3]))));
        }
    }
    float bb0 = sb2[cg*4], bb1 = sb2[cg*4+1], bb2v = sb2[cg*4+2], bb3 = sb2[cg*4+3];
    #pragma unroll
    for (int e = 0; e < 8; e++) {
        int dst = g_dst[base + eg*8 + e];
        if (dst < NN)
            red_add_v4(g_agg + (size_t)dst*64 + cg*4,
                       acc[e][0]+bb0, acc[e][1]+bb1, acc[e][2]+bb2v, acc[e][3]+bb3);
    }
}

// ---------------- GRU update (per layer); zeroes g_agg after reading ----------------
#define GRU_SMEM ((12288 + 12288) * 4)
__global__ __launch_bounds__(TPB) void tg_gru(const float* __restrict__ wi,
    const float* __restrict__ wh, const float* __restrict__ bi, const float* __restrict__ bh)
{
    extern __shared__ float sg[];
    float* sWi = sg; float* sWh = sg + 12288;
    for (int i = threadIdx.x; i < 3072; i += TPB) {
        ((float4*)sWi)[i] = ((const float4*)wi)[i];
        ((float4*)sWh)[i] = ((const float4*)wh)[i];
    }
    __syncthreads();
    int lane = threadIdx.x & 31;
    int warpsTotal = gridDim.x * (TPB/32);
    for (int node = blockIdx.x*(TPB/32) + (threadIdx.x>>5); node < NN; node += warpsTotal) {
        float* aggp = g_agg + (size_t)node*64;
        float* hp   = g_h   + (size_t)node*64;
        float a0 = aggp[lane], a1 = aggp[lane+32];
        float h0 = hp[lane],   h1 = hp[lane+32];
        aggp[lane] = 0.f; aggp[lane+32] = 0.f;
        float gi[6] = {0,0,0,0,0,0}, gh[6] = {0,0,0,0,0,0};
        #pragma unroll
        for (int k = 0; k < 32; k++) {
            float ak = __shfl_sync(0xffffffffu, a0, k);
            float hk = __shfl_sync(0xffffffffu, h0, k);
            const float* pi = sWi + k*192 + lane;
            const float* ph = sWh + k*192 + lane;
            #pragma unroll
            for (int i = 0; i < 6; i++) { gi[i] = fmaf(ak, pi[32*i], gi[i]); gh[i] = fmaf(hk, ph[32*i], gh[i]); }
        }
        #pragma unroll
        for (int k = 0; k < 32; k++) {
            float ak = __shfl_sync(0xffffffffu, a1, k);
            float hk = __shfl_sync(0xffffffffu, h1, k);
            const float* pi = sWi + (k+32)*192 + lane;
            const float* ph = sWh + (k+32)*192 + lane;
            #pragma unroll
            for (int i = 0; i < 6; i++) { gi[i] = fmaf(ak, pi[32*i], gi[i]); gh[i] = fmaf(hk, ph[32*i], gh[i]); }
        }
        float r0 = sigf(gi[0]+gh[0]+bi[lane]+bh[lane]);
        float r1 = sigf(gi[1]+gh[1]+bi[lane+32]+bh[lane+32]);
        float z0 = sigf(gi[2]+gh[2]+bi[lane+64]+bh[lane+64]);
        float z1 = sigf(gi[3]+gh[3]+bi[lane+96]+bh[lane+96]);
        float n0 = tanhf(gi[4]+bi[lane+128] + r0*(gh[4]+bh[lane+128]));
        float n1 = tanhf(gi[5]+bi[lane+160] + r1*(gh[5]+bh[lane+160]));
        hp[lane]    = (1.f-z0)*n0 + z0*h0;
        hp[lane+32] = (1.f-z1)*n1 + z1*h1;
    }
}

// ---------------- readout + correction ----------------
__global__ __launch_bounds__(TPB) void tg_readout(const float* __restrict__ x,
    const int* __restrict__ ntype, const float* __restrict__ w1, const float* __restrict__ b1,
    const float* __restrict__ w2, const float* __restrict__ b2, float* __restrict__ out)
{
    __shared__ float sw[4096], sv[64], sb[64];
    for (int i = threadIdx.x; i < 4096; i += TPB) sw[i] = w1[i];
    if (threadIdx.x < 64) { sv[threadIdx.x] = w2[threadIdx.x]; sb[threadIdx.x] = b1[threadIdx.x]; }
    __syncthreads();
    int lane = threadIdx.x & 31;
    int warpsTotal = gridDim.x * (TPB/32);
    for (int node = blockIdx.x*(TPB/32) + (threadIdx.x>>5); node < NN; node += warpsTotal) {
        const float* hp = g_h + (size_t)node*64;
        float h0 = hp[lane], h1 = hp[lane+32];
        float acc0 = 0.f, acc1 = 0.f;
        #pragma unroll
        for (int k = 0; k < 32; k++) {
            float hk = __shfl_sync(0xffffffffu, h0, k);
            acc0 = fmaf(hk, sw[k*64+lane],    acc0);
            acc1 = fmaf(hk, sw[k*64+lane+32], acc1);
        }
        #pragma unroll
        for (int k = 0; k < 32; k++) {
            float hk = __shfl_sync(0xffffffffu, h1, k);
            acc0 = fmaf(hk, sw[(k+32)*64+lane],    acc0);
            acc1 = fmaf(hk, sw[(k+32)*64+lane+32], acc1);
        }
        float t0 = fmaxf(acc0 + sb[lane],    0.f);
        float t1 = fmaxf(acc1 + sb[lane+32], 0.f);
        float p = t0*sv[lane] + t1*sv[lane+32];
        #pragma unroll
        for (int o = 16; o; o >>= 1) p += __shfl_xor_sync(0xffffffffu, p, o);
        if (lane == 0)
            out[node] = (ntype[node] == 0) ? (x[node*4] + p + b2[0]) : 0.f;
    }
}

// ---------------- launch ----------------
extern "C" void kernel_launch(void* const* d_in, const int* in_sizes, int n_in,
                              void* d_out, int out_size)
{
    const float* x        = (const float*)d_in[0];
    const int*   ntype    = (const int*)  d_in[1];
    const int*   eindex   = (const int*)  d_in[2];
    const int*   etype    = (const int*)  d_in[3];
    const float* in_w     = (const float*)d_in[4];
    const float* in_b     = (const float*)d_in[5];
    const float* ln_g     = (const float*)d_in[6];
    const float* ln_b     = (const float*)d_in[7];
    const float* mlp_w1   = (const float*)d_in[8];
    const float* mlp_b1   = (const float*)d_in[9];
    const float* mlp_w2   = (const float*)d_in[10];
    const float* mlp_b2   = (const float*)d_in[11];
    const float* gru_wi   = (const float*)d_in[12];
    const float* gru_wh   = (const float*)d_in[13];
    const float* gru_bi   = (const float*)d_in[14];
    const float* gru_bh   = (const float*)d_in[15];
    const float* ro_w1    = (const float*)d_in[16];
    const float* ro_b1    = (const float*)d_in[17];
    const float* ro_w2    = (const float*)d_in[18];
    const float* ro_b2    = (const float*)d_in[19];
    float* out = (float*)d_out;

    cudaFuncSetAttribute(tg_edge, cudaFuncAttributeMaxDynamicSharedMemorySize, EDGE_SMEM);
    cudaFuncSetAttribute(tg_gru,  cudaFuncAttributeMaxDynamicSharedMemorySize, GRU_SMEM);

    tg_input<<<304, TPB>>>(x, in_w, in_b, ln_g, ln_b);
    tg_count<<<512, TPB>>>(etype);
    tg_scan<<<1, 1>>>();
    tg_scatter<<<512, TPB>>>(etype, eindex);

    for (int l = 0; l < 3; l++) {
        tg_edge<<<NTILES_MAX, TPB, EDGE_SMEM>>>(mlp_w1 + l*2*8192, mlp_b1 + l*2*64,
                                                mlp_w2 + l*2*4096, mlp_b2 + l*2*64);
        tg_gru<<<296, TPB, GRU_SMEM>>>(gru_wi + l*12288, gru_wh + l*12288,
                                       gru_bi + l*192,   gru_bh + l*192);
    }
    tg_readout<<<304, TPB>>>(x, ntype, ro_w1, ro_b1, ro_w2, ro_b2, out);
}

// round 4
// speedup vs baseline: 1.0917x; 1.0917x over previous
#include <cuda_runtime.h>
#include <math.h>
#include <stdint.h>

#define NN      100000
#define NE      2000000
#define HH      64
#define TPB     256
#define NTILES_MAX ((NE/128) + 2)

typedef unsigned long long ull;

// ---------------- device scratch ----------------
__device__ __align__(16) float g_h[NN * HH];
__device__ __align__(16) float g_agg[NN * HH];   // invariant: zero on entry to each edge phase
__device__ int g_src[NE + 256];
__device__ int g_dst[NE + 256];
__device__ int g_cnt1;
__device__ int g_cur0, g_cur1;
__device__ int g_b0p, g_ntiles;

__device__ __forceinline__ float sigf(float v) { return 1.f / (1.f + __expf(-v)); }

__device__ __forceinline__ void red_add_v4(float* p, float a, float b, float c, float d) {
    asm volatile("red.global.add.v4.f32 [%0], {%1, %2, %3, %4};"
                 :: "l"(p), "f"(a), "f"(b), "f"(c), "f"(d) : "memory");
}

// packed fp32x2 helpers (FFMA2 path — ptxas never auto-fuses this)
__device__ __forceinline__ ull pack2(float f) {
    ull r; unsigned u = __float_as_uint(f);
    asm("mov.b64 %0, {%1, %1};" : "=l"(r) : "r"(u));
    return r;
}
__device__ __forceinline__ void fma2(ull& d, ull a, ull b) {
    asm("fma.rn.f32x2 %0, %1, %2, %0;" : "+l"(d) : "l"(a), "l"(b));
}
__device__ __forceinline__ float2 unpack2(ull v) {
    unsigned lo, hi;
    asm("mov.b64 {%0, %1}, %2;" : "=r"(lo), "=r"(hi) : "l"(v));
    float2 r; r.x = __uint_as_float(lo); r.y = __uint_as_float(hi);
    return r;
}

// ---------------- input projection: h = relu(LN(x@W+b)) ----------------
__global__ __launch_bounds__(TPB) void tg_input(const float* __restrict__ x,
    const float* __restrict__ in_w, const float* __restrict__ in_b,
    const float* __restrict__ ln_g, const float* __restrict__ ln_b)
{
    __shared__ float sw[256], sb[64], sg[64], sbn[64];
    int tid = threadIdx.x;
    if (tid < 256) sw[tid] = in_w[tid];
    if (tid < 64) { sb[tid] = in_b[tid]; sg[tid] = ln_g[tid]; sbn[tid] = ln_b[tid]; }
    __syncthreads();
    int lane = tid & 31;
    int warpsTotal = gridDim.x * (TPB / 32);
    for (int node = blockIdx.x * (TPB/32) + (tid >> 5); node < NN; node += warpsTotal) {
        float4 xv = *(const float4*)(x + node * 4);
        int c0 = lane * 2;
        float v0 = sb[c0]   + xv.x*sw[c0]   + xv.y*sw[64+c0]   + xv.z*sw[128+c0]   + xv.w*sw[192+c0];
        float v1 = sb[c0+1] + xv.x*sw[c0+1] + xv.y*sw[64+c0+1] + xv.z*sw[128+c0+1] + xv.w*sw[192+c0+1];
        float s = v0 + v1;
        #pragma unroll
        for (int o = 16; o; o >>= 1) s += __shfl_xor_sync(0xffffffffu, s, o);
        float mu = s * (1.0f/64.0f);
        float d0 = v0 - mu, d1 = v1 - mu;
        float q = d0*d0 + d1*d1;
        #pragma unroll
        for (int o = 16; o; o >>= 1) q += __shfl_xor_sync(0xffffffffu, q, o);
        float inv = rsqrtf(q * (1.0f/64.0f) + 1e-5f);
        g_h[node*64 + c0]   = fmaxf(d0*inv*sg[c0]   + sbn[c0],   0.f);
        g_h[node*64 + c0+1] = fmaxf(d1*inv*sg[c0+1] + sbn[c0+1], 0.f);
    }
}

// ---------------- edge partition by type (2 buckets, tile-aligned) ----------------
__global__ __launch_bounds__(TPB) void tg_count(const int* __restrict__ et) {
    __shared__ int sm[8];
    int tid = threadIdx.x;
    int s = 0;
    for (int e = blockIdx.x*TPB + tid; e < NE; e += gridDim.x*TPB) s += et[e];
    #pragma unroll
    for (int o = 16; o; o >>= 1) s += __shfl_xor_sync(0xffffffffu, s, o);
    if ((tid & 31) == 0) sm[tid >> 5] = s;
    __syncthreads();
    if (tid == 0) { int t = 0; for (int j = 0; j < 8; j++) t += sm[j]; atomicAdd(&g_cnt1, t); }
}

__global__ void tg_scan() {
    int c1 = g_cnt1; g_cnt1 = 0;
    int c0 = NE - c1;
    int b0p = (c0 + 127) & ~127;
    int end1 = b0p + c1;
    int nt = (end1 + 127) >> 7;
    g_b0p = b0p; g_ntiles = nt;
    g_cur0 = 0; g_cur1 = b0p;
    for (int i = c0; i < b0p; i++) { g_src[i] = 0; g_dst[i] = NN; }
    for (int i = end1; i < nt*128; i++) { g_src[i] = 0; g_dst[i] = NN; }
}

__global__ __launch_bounds__(TPB) void tg_scatter(const int* __restrict__ et,
                                                  const int* __restrict__ ei) {
    int lane = threadIdx.x & 31;
    unsigned lt = (1u << lane) - 1u;
    for (int e = blockIdx.x*TPB + threadIdx.x; e < NE; e += gridDim.x*TPB) {
        int t = et[e];                                   // NE % 32 == 0 -> full warps
        unsigned m1 = __ballot_sync(0xffffffffu, t);
        int n1 = __popc(m1);
        int b0 = 0, b1 = 0;
        if (lane == 0) {
            b0 = atomicAdd(&g_cur0, 32 - n1);
            b1 = atomicAdd(&g_cur1, n1);
        }
        b0 = __shfl_sync(0xffffffffu, b0, 0);
        b1 = __shfl_sync(0xffffffffu, b1, 0);
        int pos = t ? (b1 + __popc(m1 & lt)) : (b0 + __popc(~m1 & lt));
        g_src[pos] = ei[e];
        g_dst[pos] = ei[NE + e];
    }
}

// ---------------- edge MLP + scatter-add (per layer), FFMA2 packed ----------------
// smem floats: smiT [128k][128e] | sW1 [128][64] | sh1 [128e][66] | sW2 [64][64] | b1 | b2
#define P_MI 128
#define P_H1 66
#define OFF_W1 (128*P_MI)
#define OFF_H1 (OFF_W1 + 8192)
#define OFF_W2 (OFF_H1 + 128*P_H1)
#define OFF_B1 (OFF_W2 + 4096)
#define OFF_B2 (OFF_B1 + 64)
#define EDGE_SMEM ((OFF_B2 + 64) * 4)

__global__ __launch_bounds__(TPB, 1) void tg_edge(const float* __restrict__ w1g,
    const float* __restrict__ b1g, const float* __restrict__ w2g, const float* __restrict__ b2g)
{
    int tile = blockIdx.x;
    if (tile >= g_ntiles) return;
    int t = (tile * 128 >= g_b0p) ? 1 : 0;

    extern __shared__ float sm[];
    float* smiT = sm;
    float* sW1  = sm + OFF_W1;
    float* sh1  = sm + OFF_H1;
    float* sW2  = sm + OFF_W2;
    float* sb1  = sm + OFF_B1;
    float* sb2  = sm + OFF_B2;

    int tid = threadIdx.x;
    const float* w1 = w1g + t * 8192;
    const float* w2 = w2g + t * 4096;
    for (int i = tid; i < 2048; i += TPB) ((float4*)sW1)[i] = ((const float4*)w1)[i];
    for (int i = tid; i < 1024; i += TPB) ((float4*)sW2)[i] = ((const float4*)w2)[i];
    if (tid < 64) { sb1[tid] = b1g[t*64 + tid]; sb2[tid] = b2g[t*64 + tid]; }

    // gather: mi = [h[src] | h[dst]] transposed -> smiT[k][e]
    // warp = 32 consecutive e at fixed k-chunk -> conflict-free STS.32
    int base = tile * 128;
    for (int i = tid; i < 4096; i += TPB) {
        int e = i & 127, kc = i >> 7;               // kc 0..31
        int idx = (kc < 16) ? g_src[base + e] : g_dst[base + e];
        if (idx >= NN) idx = 0;
        float4 v = ((const float4*)(g_h + (size_t)idx*64))[kc & 15];
        float* p = smiT + (kc*4)*P_MI + e;
        p[0] = v.x; p[P_MI] = v.y; p[2*P_MI] = v.z; p[3*P_MI] = v.w;
    }
    __syncthreads();

    int eg = tid >> 4, cg = tid & 15;               // 16 edge groups x 16 col groups
    int e0 = eg * 8, c0 = cg * 4;

    // ---- stage 1: edge-pair packed ----
    ull acc[4][4];
    #pragma unroll
    for (int p = 0; p < 4; p++)
        #pragma unroll
        for (int j = 0; j < 4; j++) acc[p][j] = 0ull;

    const float* miB = smiT + e0;
    const float* wB  = sW1 + c0;
    #pragma unroll 4
    for (int k = 0; k < 128; k++) {
        ull m0 = *(const ull*)(miB + k*P_MI + 0);
        ull m1 = *(const ull*)(miB + k*P_MI + 2);
        ull m2 = *(const ull*)(miB + k*P_MI + 4);
        ull m3 = *(const ull*)(miB + k*P_MI + 6);
        float4 w = *(const float4*)(wB + k*64);
        ull w0 = pack2(w.x), w1p = pack2(w.y), w2p = pack2(w.z), w3p = pack2(w.w);
        fma2(acc[0][0], m0, w0); fma2(acc[0][1], m0, w1p); fma2(acc[0][2], m0, w2p); fma2(acc[0][3], m0, w3p);
        fma2(acc[1][0], m1, w0); fma2(acc[1][1], m1, w1p); fma2(acc[1][2], m1, w2p); fma2(acc[1][3], m1, w3p);
        fma2(acc[2][0], m2, w0); fma2(acc[2][1], m2, w1p); fma2(acc[2][2], m2, w2p); fma2(acc[2][3], m2, w3p);
        fma2(acc[3][0], m3, w0); fma2(acc[3][1], m3, w1p); fma2(acc[3][2], m3, w2p); fma2(acc[3][3], m3, w3p);
    }
    #pragma unroll
    for (int p = 0; p < 4; p++)
        #pragma unroll
        for (int j = 0; j < 4; j++) {
            float2 r = unpack2(acc[p][j]);
            int c = c0 + j;
            float b = sb1[c];
            sh1[(e0 + 2*p    )*P_H1 + c] = fmaxf(r.x + b, 0.f);
            sh1[(e0 + 2*p + 1)*P_H1 + c] = fmaxf(r.y + b, 0.f);
        }
    __syncthreads();

    // ---- stage 2: col-pair packed ----
    ull a2[8][2];
    #pragma unroll
    for (int e = 0; e < 8; e++) { a2[e][0] = 0ull; a2[e][1] = 0ull; }
    const float* h1B = sh1 + e0 * P_H1;
    const float* w2B = sW2 + c0;
    #pragma unroll 4
    for (int k = 0; k < 64; k++) {
        ull wp0 = *(const ull*)(w2B + k*64);
        ull wp1 = *(const ull*)(w2B + k*64 + 2);
        #pragma unroll
        for (int e = 0; e < 8; e++) {
            ull me = pack2(h1B[e*P_H1 + k]);
            fma2(a2[e][0], me, wp0);
            fma2(a2[e][1], me, wp1);
        }
    }
    float bb0 = sb2[c0], bb1 = sb2[c0+1], bb2v = sb2[c0+2], bb3 = sb2[c0+3];
    #pragma unroll
    for (int e = 0; e < 8; e++) {
        int dst = g_dst[base + e0 + e];
        if (dst < NN) {
            float2 lo = unpack2(a2[e][0]);
            float2 hi = unpack2(a2[e][1]);
            red_add_v4(g_agg + (size_t)dst*64 + c0,
                       lo.x + bb0, lo.y + bb1, hi.x + bb2v, hi.y + bb3);
        }
    }
}

// ---------------- GRU update (per layer), FFMA2 packed; zeroes g_agg ----------------
#define GRU_SMEM ((12288 + 12288) * 4)
__global__ __launch_bounds__(TPB) void tg_gru(const float* __restrict__ wi,
    const float* __restrict__ wh, const float* __restrict__ bi, const float* __restrict__ bh)
{
    extern __shared__ float sg[];
    float* sWi = sg; float* sWh = sg + 12288;
    for (int i = threadIdx.x; i < 3072; i += TPB) {
        ((float4*)sWi)[i] = ((const float4*)wi)[i];
        ((float4*)sWh)[i] = ((const float4*)wh)[i];
    }
    __syncthreads();
    int lane = threadIdx.x & 31;
    int warpsTotal = gridDim.x * (TPB/32);
    for (int node = blockIdx.x*(TPB/32) + (threadIdx.x>>5); node < NN; node += warpsTotal) {
        float* aggp = g_agg + (size_t)node*64;
        float* hp   = g_h   + (size_t)node*64;
        float a0 = aggp[lane], a1 = aggp[lane+32];
        float h0 = hp[lane],   h1 = hp[lane+32];
        aggp[lane] = 0.f; aggp[lane+32] = 0.f;
        float2 hpair = *(const float2*)(hp + 2*lane);
        ull gi[3] = {0,0,0}, gh[3] = {0,0,0};
        #pragma unroll
        for (int k = 0; k < 32; k++) {
            ull pa = pack2(__shfl_sync(0xffffffffu, a0, k));
            ull ph = pack2(__shfl_sync(0xffffffffu, h0, k));
            const float* pi = sWi + k*192 + 2*lane;
            const float* pw = sWh + k*192 + 2*lane;
            #pragma unroll
            for (int g = 0; g < 3; g++) {
                fma2(gi[g], pa, *(const ull*)(pi + 64*g));
                fma2(gh[g], ph, *(const ull*)(pw + 64*g));
            }
        }
        #pragma unroll
        for (int k = 0; k < 32; k++) {
            ull pa = pack2(__shfl_sync(0xffffffffu, a1, k));
            ull ph = pack2(__shfl_sync(0xffffffffu, h1, k));
            const float* pi = sWi + (k+32)*192 + 2*lane;
            const float* pw = sWh + (k+32)*192 + 2*lane;
            #pragma unroll
            for (int g = 0; g < 3; g++) {
                fma2(gi[g], pa, *(const ull*)(pi + 64*g));
                fma2(gh[g], ph, *(const ull*)(pw + 64*g));
            }
        }
        float2 vir = unpack2(gi[0]), vhr = unpack2(gh[0]);
        float2 viz = unpack2(gi[1]), vhz = unpack2(gh[1]);
        float2 vin = unpack2(gi[2]), vhn = unpack2(gh[2]);
        float2 bir = *(const float2*)(bi + 2*lane),        bhr = *(const float2*)(bh + 2*lane);
        float2 biz = *(const float2*)(bi + 64 + 2*lane),   bhz = *(const float2*)(bh + 64 + 2*lane);
        float2 bin = *(const float2*)(bi + 128 + 2*lane),  bhn = *(const float2*)(bh + 128 + 2*lane);
        float r0 = sigf(vir.x + vhr.x + bir.x + bhr.x);
        float r1 = sigf(vir.y + vhr.y + bir.y + bhr.y);
        float z0 = sigf(viz.x + vhz.x + biz.x + bhz.x);
        float z1 = sigf(viz.y + vhz.y + biz.y + bhz.y);
        float n0 = tanhf(vin.x + bin.x + r0*(vhn.x + bhn.x));
        float n1 = tanhf(vin.y + bin.y + r1*(vhn.y + bhn.y));
        float2 outp;
        outp.x = (1.f - z0)*n0 + z0*hpair.x;
        outp.y = (1.f - z1)*n1 + z1*hpair.y;
        *(float2*)(hp + 2*lane) = outp;
    }
}

// ---------------- readout + correction ----------------
__global__ __launch_bounds__(TPB) void tg_readout(const float* __restrict__ x,
    const int* __restrict__ ntype, const float* __restrict__ w1, const float* __restrict__ b1,
    const float* __restrict__ w2, const float* __restrict__ b2, float* __restrict__ out)
{
    __shared__ float sw[4096], sv[64], sb[64];
    for (int i = threadIdx.x; i < 4096; i += TPB) sw[i] = w1[i];
    if (threadIdx.x < 64) { sv[threadIdx.x] = w2[threadIdx.x]; sb[threadIdx.x] = b1[threadIdx.x]; }
    __syncthreads();
    int lane = threadIdx.x & 31;
    int warpsTotal = gridDim.x * (TPB/32);
    for (int node = blockIdx.x*(TPB/32) + (threadIdx.x>>5); node < NN; node += warpsTotal) {
        const float* hp = g_h + (size_t)node*64;
        float h0 = hp[lane], h1 = hp[lane+32];
        float acc0 = 0.f, acc1 = 0.f;
        #pragma unroll
        for (int k = 0; k < 32; k++) {
            float hk = __shfl_sync(0xffffffffu, h0, k);
            acc0 = fmaf(hk, sw[k*64+lane],    acc0);
            acc1 = fmaf(hk, sw[k*64+lane+32], acc1);
        }
        #pragma unroll
        for (int k = 0; k < 32; k++) {
            float hk = __shfl_sync(0xffffffffu, h1, k);
            acc0 = fmaf(hk, sw[(k+32)*64+lane],    acc0);
            acc1 = fmaf(hk, sw[(k+32)*64+lane+32], acc1);
        }
        float t0 = fmaxf(acc0 + sb[lane],    0.f);
        float t1 = fmaxf(acc1 + sb[lane+32], 0.f);
        float p = t0*sv[lane] + t1*sv[lane+32];
        #pragma unroll
        for (int o = 16; o; o >>= 1) p += __shfl_xor_sync(0xffffffffu, p, o);
        if (lane == 0)
            out[node] = (ntype[node] == 0) ? (x[node*4] + p + b2[0]) : 0.f;
    }
}

// ---------------- launch ----------------
extern "C" void kernel_launch(void* const* d_in, const int* in_sizes, int n_in,
                              void* d_out, int out_size)
{
    const float* x        = (const float*)d_in[0];
    const int*   ntype    = (const int*)  d_in[1];
    const int*   eindex   = (const int*)  d_in[2];
    const int*   etype    = (const int*)  d_in[3];
    const float* in_w     = (const float*)d_in[4];
    const float* in_b     = (const float*)d_in[5];
    const float* ln_g     = (const float*)d_in[6];
    const float* ln_b     = (const float*)d_in[7];
    const float* mlp_w1   = (const float*)d_in[8];
    const float* mlp_b1   = (const float*)d_in[9];
    const float* mlp_w2   = (const float*)d_in[10];
    const float* mlp_b2   = (const float*)d_in[11];
    const float* gru_wi   = (const float*)d_in[12];
    const float* gru_wh   = (const float*)d_in[13];
    const float* gru_bi   = (const float*)d_in[14];
    const float* gru_bh   = (const float*)d_in[15];
    const float* ro_w1    = (const float*)d_in[16];
    const float* ro_b1    = (const float*)d_in[17];
    const float* ro_w2    = (const float*)d_in[18];
    const float* ro_b2    = (const float*)d_in[19];
    float* out = (float*)d_out;

    cudaFuncSetAttribute(tg_edge, cudaFuncAttributeMaxDynamicSharedMemorySize, EDGE_SMEM);
    cudaFuncSetAttribute(tg_gru,  cudaFuncAttributeMaxDynamicSharedMemorySize, GRU_SMEM);

    tg_input<<<304, TPB>>>(x, in_w, in_b, ln_g, ln_b);
    tg_count<<<512, TPB>>>(etype);
    tg_scan<<<1, 1>>>();
    tg_scatter<<<512, TPB>>>(etype, eindex);

    for (int l = 0; l < 3; l++) {
        tg_edge<<<NTILES_MAX, TPB, EDGE_SMEM>>>(mlp_w1 + l*2*8192, mlp_b1 + l*2*64,
                                                mlp_w2 + l*2*4096, mlp_b2 + l*2*64);
        tg_gru<<<296, TPB, GRU_SMEM>>>(gru_wi + l*12288, gru_wh + l*12288,
                                       gru_bi + l*192,   gru_bh + l*192);
    }
    tg_readout<<<304, TPB>>>(x, ntype, ro_w1, ro_b1, ro_w2, ro_b2, out);
}